// round 1
// baseline (speedup 1.0000x reference)
#include <cuda_runtime.h>
#include <math.h>

// ---------------- problem constants ----------------
constexpr int Bb   = 4;
constexpr int NIN  = 6170;
constexpr int Lf   = 768;
constexpr int Dd   = 512;
constexpr int NT   = 6264;   // tokens incl cls (10 + 169 + 6084 + 1)
constexpr int NP   = 6400;   // padded length for attention
constexpr int PADT = 136;    // front zero-pad
constexpr int HH   = 8;
constexpr int DH   = 64;
constexpr int LM   = 256;    // landmarks
constexpr int LFAC = 25;     // NP / LM
constexpr long long QSZ = (long long)Bb*HH*NP*DH; // 13107200

// ---------------- device scratch ----------------
__device__ float g_h0 [12636160];   // (4,6170,512)
__device__ float g_H  [12828672];   // (4,6264,512)
__device__ float g_H2 [12828672];
__device__ float g_XP [13107200];   // (4,6400,512) layernormed + zero pad
__device__ float g_QKV[39321600];   // Q|K|V each (4,8,6400,64)
__device__ float g_QL [524288];     // (32,256,64)
__device__ float g_KL [524288];
__device__ float g_S1 [52428800];   // (32,6400,256)
__device__ float g_S3 [52428800];   // (32,256,6400)
__device__ float g_A2 [2097152];    // (32,256,256)
__device__ float g_AZ [2097152];
__device__ float g_T1 [2097152];
__device__ float g_T2 [2097152];
__device__ float g_Za [2097152];
__device__ float g_Zb [2097152];
__device__ float g_RED[64];         // pinv norm partials
__device__ float g_A3V[524288];     // (32,256,64)
__device__ float g_W2 [524288];
__device__ float g_PRT[4194304];    // split-K partials (32*8,256,64)
__device__ float g_ATT[13107200];   // (4,6400,512) attn output (token-major)

// ---------------- batched SGEMM ----------------
struct GP {
  const float* A; long long sA; int lda;
  const float* B; long long sB; int ldb;
  float*       C; long long sC; int ldc;
  int M, N, K, ksplit, epi;
  const float* bias; float alpha; float* out2;
};
// epi: 0=store 1=relu+bias 2=qkv-scatter 3=alpha*I-acc 4=alpha*acc
//      5=attnT-scatter 6=residual+bias add

template<int BM,int BN,int BK,int TM,int TN,bool TB>
__global__ void __launch_bounds__(256) sgemm_k(GP p){
  __shared__ float As[BK][BM];
  __shared__ float Bs[BK][BN];
  constexpr int TX = BN/TN, TY = BM/TM;
  static_assert(TX*TY == 256, "thread cfg");
  const int tid = threadIdx.x;
  const int tx = tid % TX, ty = tid / TX;
  const int z  = blockIdx.z;
  const int zb = z / p.ksplit, ks = z % p.ksplit;
  const int klen = p.K / p.ksplit, kb = ks*klen;
  const float* A  = p.A + (long long)zb * p.sA;
  const float* Bm = p.B + (long long)zb * p.sB;
  const int row0 = blockIdx.y * BM, col0 = blockIdx.x * BN;

  float acc[TM][TN];
  #pragma unroll
  for(int i=0;i<TM;i++)
    #pragma unroll
    for(int j=0;j<TN;j++) acc[i][j]=0.f;

  for(int kt = kb; kt < kb+klen; kt += BK){
    #pragma unroll 4
    for(int i=tid;i<BM*BK;i+=256){
      int m=i/BK, k=i%BK; int gm=row0+m;
      As[k][m] = (gm < p.M) ? A[(long long)gm*p.lda + kt + k] : 0.f;
    }
    if (TB){
      #pragma unroll 4
      for(int i=tid;i<BN*BK;i+=256){
        int n=i/BK, k=i%BK; int gn=col0+n;
        Bs[k][n] = (gn < p.N) ? Bm[(long long)gn*p.ldb + kt + k] : 0.f;
      }
    } else {
      #pragma unroll 4
      for(int i=tid;i<BN*BK;i+=256){
        int k=i/BN, n=i%BN; int gn=col0+n;
        Bs[k][n] = (gn < p.N) ? Bm[(long long)(kt+k)*p.ldb + gn] : 0.f;
      }
    }
    __syncthreads();
    #pragma unroll
    for(int kk=0;kk<BK;kk++){
      float a[TM], bv[TN];
      #pragma unroll
      for(int i=0;i<TM;i++) a[i]=As[kk][ty*TM+i];
      #pragma unroll
      for(int j=0;j<TN;j++) bv[j]=Bs[kk][tx*TN+j];
      #pragma unroll
      for(int i=0;i<TM;i++)
        #pragma unroll
        for(int j=0;j<TN;j++) acc[i][j] += a[i]*bv[j];
    }
    __syncthreads();
  }

  #pragma unroll
  for(int i=0;i<TM;i++){
    int gm = row0 + ty*TM + i;
    if (gm >= p.M) continue;
    #pragma unroll
    for(int j=0;j<TN;j++){
      int gn = col0 + tx*TN + j;
      if (gn >= p.N) continue;
      float v = acc[i][j];
      switch(p.epi){
        case 0:
          p.C[(long long)z*p.sC + (long long)gm*p.ldc + gn] = v; break;
        case 1: {
          v += p.bias[gn];
          p.C[(long long)z*p.sC + (long long)gm*p.ldc + gn] = v>0.f?v:0.f;
        } break;
        case 2: { // qkv scatter, z = batch b
          int which = gn >> 9; int hh = (gn >> 6) & 7; int d = gn & 63;
          float s = (which==0) ? p.alpha : 1.f;
          p.out2[(long long)which*QSZ + (((long long)z*HH+hh)*NP + gm)*DH + d] = s*v;
        } break;
        case 3:
          p.C[(long long)z*p.sC + (long long)gm*p.ldc + gn] = (gm==gn?p.alpha:0.f) - v; break;
        case 4:
          p.C[(long long)z*p.sC + (long long)gm*p.ldc + gn] = p.alpha * v; break;
        case 5: { // attnT scatter, z = b*8+h, gm = token-136
          int b = z >> 3, hh = z & 7;
          p.out2[((long long)b*NP + (PADT+gm))*Dd + hh*DH + gn] = v;
        } break;
        case 6: { // residual add into H
          long long o = (long long)z*p.sC + (long long)gm*p.ldc + gn;
          p.C[o] += v + p.bias[gn];
        } break;
      }
    }
  }
}

// ---------------- small kernels ----------------
__global__ void build_H_k(const float* __restrict__ h0, const float* __restrict__ cls,
                          float* __restrict__ Hb){
  int t = blockIdx.x, b = blockIdx.y;
  int src;
  if (t == 0) src = -1;
  else if (t <= 10) src = t-1;
  else if (t < 180){ int j=t-11; src = 10 + (j<160 ? j : j-160); }
  else             { int j=t-180; src = 170 + (j<6000 ? j : j-6000); }
  const float* s = (src<0) ? cls : h0 + ((long long)b*NIN + src)*Dd;
  float* d = Hb + ((long long)b*NT + t)*Dd;
  for(int c=threadIdx.x;c<Dd;c+=256) d[c]=s[c];
}

__global__ void ln_pad_k(const float* __restrict__ Hin, const float* __restrict__ g,
                         const float* __restrict__ bb, float* __restrict__ XP){
  __shared__ float red[256];
  int n = blockIdx.x, b = blockIdx.y, t = threadIdx.x;
  float* out = XP + ((long long)b*NP + n)*Dd;
  if (n < PADT){ out[t]=0.f; out[t+256]=0.f; return; }
  const float* x = Hin + ((long long)b*NT + (n-PADT))*Dd;
  float v0=x[t], v1=x[t+256];
  red[t]=v0+v1; __syncthreads();
  for(int o=128;o>0;o>>=1){ if(t<o) red[t]+=red[t+o]; __syncthreads(); }
  float mu = red[0]*(1.f/512.f); __syncthreads();
  float d0=v0-mu, d1=v1-mu;
  red[t]=d0*d0+d1*d1; __syncthreads();
  for(int o=128;o>0;o>>=1){ if(t<o) red[t]+=red[t+o]; __syncthreads(); }
  float rs = rsqrtf(red[0]*(1.f/512.f)+1e-5f);
  out[t]     = d0*rs*g[t]     + bb[t];
  out[t+256] = d1*rs*g[t+256] + bb[t+256];
}

__global__ void landmarks_k(const float* __restrict__ Q, const float* __restrict__ K,
                            float* __restrict__ QL, float* __restrict__ KL){
  int idx = blockIdx.x*256 + threadIdx.x;           // 32*256*64 = 524288
  int d = idx & 63; int i = (idx>>6) & 255; int bh = idx >> 14;
  long long base = ((long long)bh*NP + (long long)i*LFAC)*DH + d;
  float sq=0.f, sk=0.f;
  #pragma unroll
  for(int j=0;j<LFAC;j++){ sq += Q[base + (long long)j*DH]; sk += K[base + (long long)j*DH]; }
  QL[idx] = sq*(1.f/LFAC); KL[idx] = sk*(1.f/LFAC);
}

__global__ void softmax_k(float* __restrict__ x, long long bstride, int n){
  __shared__ float red[256];
  float* row = x + (long long)blockIdx.y*bstride + (long long)blockIdx.x*n;
  int t = threadIdx.x;
  float mx = -3.4e38f;
  for(int i=t;i<n;i+=256) mx = fmaxf(mx, row[i]);
  red[t]=mx; __syncthreads();
  for(int o=128;o>0;o>>=1){ if(t<o) red[t]=fmaxf(red[t],red[t+o]); __syncthreads(); }
  mx = red[0]; __syncthreads();
  float s=0.f;
  for(int i=t;i<n;i+=256){ float e=expf(row[i]-mx); row[i]=e; s+=e; }
  red[t]=s; __syncthreads();
  for(int o=128;o>0;o>>=1){ if(t<o) red[t]+=red[t+o]; __syncthreads(); }
  float inv = 1.f/red[0];
  for(int i=t;i<n;i+=256) row[i]*=inv;
}

// pinv norm: per-bh partial maxima (global max taken in next kernel)
__global__ void pinv_part_k(const float* __restrict__ A, float* __restrict__ red){
  __shared__ float s1[256], s2[256];
  int bh = blockIdx.x, t = threadIdx.x;
  const float* a = A + (long long)bh*65536;
  float rs=0.f, cs=0.f;
  for(int c=0;c<256;c++) rs += fabsf(a[t*256+c]);
  for(int r=0;r<256;r++) cs += fabsf(a[r*256+t]);
  s1[t]=rs; s2[t]=cs; __syncthreads();
  for(int o=128;o>0;o>>=1){ if(t<o){ s1[t]=fmaxf(s1[t],s1[t+o]); s2[t]=fmaxf(s2[t],s2[t+o]); } __syncthreads(); }
  if(t==0){ red[bh]=s1[0]; red[32+bh]=s2[0]; }
}

__global__ void pinv_trans_k(const float* __restrict__ A, const float* __restrict__ red,
                             float* __restrict__ Z){
  int bh = blockIdx.x, t = threadIdx.x;
  float col=0.f, row=0.f;
  for(int i=0;i<32;i++){ col=fmaxf(col,red[i]); row=fmaxf(row,red[32+i]); }
  float inv = 1.f/(col*row);
  const float* a = A + (long long)bh*65536;
  float* z = Z + (long long)bh*65536;
  for(int i=0;i<256;i++) z[i*256+t] = a[t*256+i]*inv;   // z = a^T * inv
}

__global__ void diag7_k(const float* __restrict__ AZ, float* __restrict__ T1){
  long long i = (long long)blockIdx.x*256 + threadIdx.x; // 32*65536
  int e = (int)(i & 65535); int r = e>>8, c = e&255;
  T1[i] = (r==c ? 7.f : 0.f) - AZ[i];
}

__global__ void reduce8_k(const float* __restrict__ P, float* __restrict__ O){
  long long i = (long long)blockIdx.x*256 + threadIdx.x; // 32*16384
  int zb = (int)(i>>14); int e = (int)(i & 16383);
  float s=0.f;
  #pragma unroll
  for(int k=0;k<8;k++) s += P[(((long long)zb*8+k)<<14) + e];
  O[i]=s;
}

__global__ void dwconv_k(const float* __restrict__ V, const float* __restrict__ w,
                         float* __restrict__ att){
  int bh = blockIdx.y; int b = bh>>3, h = bh&7;
  int lt = threadIdx.x; int sub = lt>>6; int d = lt&63;
  int n = PADT + blockIdx.x*4 + sub;
  const float* vb = V + (long long)bh*NP*DH;
  const float* wh = w + h*33;
  float acc=0.f;
  #pragma unroll
  for(int t=0;t<33;t++){
    int nn = n + t - 16;
    if(nn>=0 && nn<NP) acc += vb[(long long)nn*DH + d]*wh[t];
  }
  att[((long long)b*NP + n)*Dd + h*DH + d] += acc;
}

__global__ void copyrows_k(const float* __restrict__ Hin, float* __restrict__ Hout){
  int t = blockIdx.x, b = blockIdx.y;
  long long o = ((long long)b*NT + t)*Dd;
  Hout[o+threadIdx.x]     = Hin[o+threadIdx.x];
  Hout[o+threadIdx.x+256] = Hin[o+threadIdx.x+256];
}

__global__ void ppeg_k(const float* __restrict__ Hin, float* __restrict__ Hout,
                       int tok0, int S,
                       const float* __restrict__ w7, const float* __restrict__ b7,
                       const float* __restrict__ w5, const float* __restrict__ b5,
                       const float* __restrict__ w3, const float* __restrict__ b3){
  int p = blockIdx.x, b = blockIdx.y;
  int y = p / S, x = p % S;
  const float* base = Hin + ((long long)b*NT + tok0)*Dd;
  float* out = Hout + ((long long)b*NT + tok0 + p)*Dd;
  for(int c=threadIdx.x;c<Dd;c+=blockDim.x){
    float acc = base[(long long)p*Dd + c] + b7[c] + b5[c] + b3[c];
    const float* wc7 = w7 + c*49;
    const float* wc5 = w5 + c*25;
    const float* wc3 = w3 + c*9;
    #pragma unroll
    for(int ky=0;ky<7;ky++){
      int yy=y+ky-3; if(yy<0||yy>=S) continue;
      #pragma unroll
      for(int kx=0;kx<7;kx++){
        int xx=x+kx-3; if(xx<0||xx>=S) continue;
        acc += base[(long long)(yy*S+xx)*Dd + c]*wc7[ky*7+kx];
      }
    }
    #pragma unroll
    for(int ky=0;ky<5;ky++){
      int yy=y+ky-2; if(yy<0||yy>=S) continue;
      #pragma unroll
      for(int kx=0;kx<5;kx++){
        int xx=x+kx-2; if(xx<0||xx>=S) continue;
        acc += base[(long long)(yy*S+xx)*Dd + c]*wc5[ky*5+kx];
      }
    }
    #pragma unroll
    for(int ky=0;ky<3;ky++){
      int yy=y+ky-1; if(yy<0||yy>=S) continue;
      #pragma unroll
      for(int kx=0;kx<3;kx++){
        int xx=x+kx-1; if(xx<0||xx>=S) continue;
        acc += base[(long long)(yy*S+xx)*Dd + c]*wc3[ky*3+kx];
      }
    }
    out[c]=acc;
  }
}

__global__ void final_ln_k(const float* __restrict__ Hb, const float* __restrict__ g,
                           const float* __restrict__ bb, float* __restrict__ out){
  __shared__ float red[256];
  int b = blockIdx.x, t = threadIdx.x;
  const float* x = Hb + (long long)b*NT*Dd; // row 0
  float v0=x[t], v1=x[t+256];
  red[t]=v0+v1; __syncthreads();
  for(int o=128;o>0;o>>=1){ if(t<o) red[t]+=red[t+o]; __syncthreads(); }
  float mu = red[0]*(1.f/512.f); __syncthreads();
  float d0=v0-mu, d1=v1-mu;
  red[t]=d0*d0+d1*d1; __syncthreads();
  for(int o=128;o>0;o>>=1){ if(t<o) red[t]+=red[t+o]; __syncthreads(); }
  float rs = rsqrtf(red[0]*(1.f/512.f)+1e-5f);
  out[b*Dd + t]     = d0*rs*g[t]     + bb[t];
  out[b*Dd + t+256] = d1*rs*g[t+256] + bb[t+256];
}

// ---------------- host side ----------------
enum CfgT { CBIG=0, CSMALL=1, CN64=2 };

static void gemm(CfgT c, bool tb, GP p, int batches){
  int BM = (c==CSMALL)?64:128;
  int BN = (c==CBIG)?128:64;
  dim3 g((p.N+BN-1)/BN, (p.M+BM-1)/BM, batches*p.ksplit);
  if(c==CBIG){
    if(tb) sgemm_k<128,128,8,8,8,true ><<<g,256>>>(p);
    else   sgemm_k<128,128,8,8,8,false><<<g,256>>>(p);
  } else if(c==CSMALL){
    if(tb) sgemm_k<64,64,16,4,4,true ><<<g,256>>>(p);
    else   sgemm_k<64,64,16,4,4,false><<<g,256>>>(p);
  } else {
    if(tb) sgemm_k<128,64,8,8,4,true ><<<g,256>>>(p);
    else   sgemm_k<128,64,8,8,4,false><<<g,256>>>(p);
  }
}

struct Scratch {
  float *h0,*H,*H2,*XP,*QKV,*QL,*KL,*S1,*S3,*A2,*AZ,*T1,*T2,*Za,*Zb,*RED,*A3V,*W2,*PRT,*ATT;
};

static void attn_layer(float* Hbuf, const float* ng, const float* nb,
                       const float* qkvw, const float* ow, const float* ob,
                       const float* rw, const Scratch& s){
  float* Q  = s.QKV;
  float* Kp = s.QKV + QSZ;
  float* V  = s.QKV + 2*QSZ;
  GP p{};

  ln_pad_k<<<dim3(NP,Bb),256>>>(Hbuf, ng, nb, s.XP);

  // QKV: (4) x [6400,512] @ [512,1536] -> scatter heads
  p = {s.XP,(long long)NP*Dd,Dd, qkvw,0,3*Dd, nullptr,0,0, NP,3*Dd,Dd, 1,2, nullptr,0.125f, s.QKV};
  gemm(CBIG,false,p,Bb);

  landmarks_k<<<2048,256>>>(Q, Kp, s.QL, s.KL);

  // sim2 = QL @ KL^T  (32 x 256x256, K=64)
  p = {s.QL,(long long)LM*DH,DH, s.KL,(long long)LM*DH,DH, s.A2,(long long)LM*LM,LM, LM,LM,DH,1,0,nullptr,0.f,nullptr};
  gemm(CSMALL,true,p,32);
  softmax_k<<<dim3(LM,32),256>>>(s.A2,(long long)LM*LM,LM);

  // pinv init: global col/row scalars, z0 = a2^T/(col*row)
  pinv_part_k<<<32,256>>>(s.A2, s.RED);
  pinv_trans_k<<<32,256>>>(s.A2, s.RED, s.Za);
  float* zc = s.Za; float* zn = s.Zb;
  for(int it=0;it<6;it++){
    p = {s.A2,65536,LM, zc,65536,LM, s.AZ,65536,LM, LM,LM,LM,1,0,nullptr,0.f,nullptr};
    gemm(CSMALL,false,p,32);                                  // AZ = a2 @ z
    diag7_k<<<8192,256>>>(s.AZ, s.T1);                        // T1 = 7I - AZ
    p = {s.AZ,65536,LM, s.T1,65536,LM, s.T2,65536,LM, LM,LM,LM,1,3,nullptr,15.f,nullptr};
    gemm(CSMALL,false,p,32);                                  // T2 = 15I - AZ@T1
    p = {s.AZ,65536,LM, s.T2,65536,LM, s.T1,65536,LM, LM,LM,LM,1,3,nullptr,13.f,nullptr};
    gemm(CSMALL,false,p,32);                                  // T1 = 13I - AZ@T2
    p = {zc,65536,LM, s.T1,65536,LM, zn,65536,LM, LM,LM,LM,1,4,nullptr,0.25f,nullptr};
    gemm(CSMALL,false,p,32);                                  // zn = 0.25 z@T1
    float* t=zc; zc=zn; zn=t;
  }

  // sim1 = q @ KL^T (only tokens >= PADT)
  p = {Q+(long long)PADT*DH,(long long)NP*DH,DH, s.KL,(long long)LM*DH,DH,
       s.S1+(long long)PADT*LM,(long long)NP*LM,LM, NT,LM,DH,1,0,nullptr,0.f,nullptr};
  gemm(CBIG,true,p,32);
  softmax_k<<<dim3(NT,32),256>>>(s.S1+(long long)PADT*LM,(long long)NP*LM,LM);

  // sim3 = QL @ K^T
  p = {s.QL,(long long)LM*DH,DH, Kp,(long long)NP*DH,DH, s.S3,(long long)LM*NP,NP, LM,NP,DH,1,0,nullptr,0.f,nullptr};
  gemm(CBIG,true,p,32);
  softmax_k<<<dim3(LM,32),256>>>(s.S3,(long long)LM*NP,NP);

  // a3v = a3 @ v  (split-K 8)
  p = {s.S3,(long long)LM*NP,NP, V,(long long)NP*DH,DH, s.PRT,(long long)LM*DH,DH, LM,DH,NP,8,0,nullptr,0.f,nullptr};
  gemm(CSMALL,false,p,32);
  reduce8_k<<<2048,256>>>(s.PRT, s.A3V);

  // w2 = Z @ a3v
  p = {zc,65536,LM, s.A3V,(long long)LM*DH,DH, s.W2,(long long)LM*DH,DH, LM,DH,LM,1,0,nullptr,0.f,nullptr};
  gemm(CSMALL,false,p,32);

  // attn = a1 @ w2 -> token-major scatter
  p = {s.S1+(long long)PADT*LM,(long long)NP*LM,LM, s.W2,(long long)LM*DH,DH, nullptr,0,0,
       NT,DH,LM,1,5,nullptr,0.f,s.ATT};
  gemm(CN64,false,p,32);

  dwconv_k<<<dim3(1566,32),256>>>(V, rw, s.ATT);

  // out proj + residual add into Hbuf
  p = {s.ATT+(long long)PADT*Dd,(long long)NP*Dd,Dd, ow,0,Dd, Hbuf,(long long)NT*Dd,Dd,
       NT,Dd,Dd,1,6,ob,0.f,nullptr};
  gemm(CBIG,false,p,Bb);
}

extern "C" void kernel_launch(void* const* d_in, const int* in_sizes, int n_in,
                              void* d_out, int out_size){
  const float* x        = (const float*)d_in[0];
  const float* fc1_w    = (const float*)d_in[1];
  const float* fc1_b    = (const float*)d_in[2];
  const float* cls_tok  = (const float*)d_in[3];
  const float* l1_ng    = (const float*)d_in[4];
  const float* l1_nb    = (const float*)d_in[5];
  const float* l1_qkv   = (const float*)d_in[6];
  const float* l1_ow    = (const float*)d_in[7];
  const float* l1_ob    = (const float*)d_in[8];
  const float* l1_rw    = (const float*)d_in[9];
  const float* ct_w7    = (const float*)d_in[10];
  const float* ct_b7    = (const float*)d_in[11];
  const float* ct_w5    = (const float*)d_in[12];
  const float* ct_b5    = (const float*)d_in[13];
  const float* ct_w3    = (const float*)d_in[14];
  const float* ct_b3    = (const float*)d_in[15];
  const float* pth_w7   = (const float*)d_in[16];
  const float* pth_b7   = (const float*)d_in[17];
  const float* pth_w5   = (const float*)d_in[18];
  const float* pth_b5   = (const float*)d_in[19];
  const float* pth_w3   = (const float*)d_in[20];
  const float* pth_b3   = (const float*)d_in[21];
  const float* l2_ng    = (const float*)d_in[22];
  const float* l2_nb    = (const float*)d_in[23];
  const float* l2_qkv   = (const float*)d_in[24];
  const float* l2_ow    = (const float*)d_in[25];
  const float* l2_ob    = (const float*)d_in[26];
  const float* l2_rw    = (const float*)d_in[27];
  const float* norm_g   = (const float*)d_in[28];
  const float* norm_b   = (const float*)d_in[29];

  Scratch s;
  cudaGetSymbolAddress((void**)&s.h0 , g_h0 );
  cudaGetSymbolAddress((void**)&s.H  , g_H  );
  cudaGetSymbolAddress((void**)&s.H2 , g_H2 );
  cudaGetSymbolAddress((void**)&s.XP , g_XP );
  cudaGetSymbolAddress((void**)&s.QKV, g_QKV);
  cudaGetSymbolAddress((void**)&s.QL , g_QL );
  cudaGetSymbolAddress((void**)&s.KL , g_KL );
  cudaGetSymbolAddress((void**)&s.S1 , g_S1 );
  cudaGetSymbolAddress((void**)&s.S3 , g_S3 );
  cudaGetSymbolAddress((void**)&s.A2 , g_A2 );
  cudaGetSymbolAddress((void**)&s.AZ , g_AZ );
  cudaGetSymbolAddress((void**)&s.T1 , g_T1 );
  cudaGetSymbolAddress((void**)&s.T2 , g_T2 );
  cudaGetSymbolAddress((void**)&s.Za , g_Za );
  cudaGetSymbolAddress((void**)&s.Zb , g_Zb );
  cudaGetSymbolAddress((void**)&s.RED, g_RED);
  cudaGetSymbolAddress((void**)&s.A3V, g_A3V);
  cudaGetSymbolAddress((void**)&s.W2 , g_W2 );
  cudaGetSymbolAddress((void**)&s.PRT, g_PRT);
  cudaGetSymbolAddress((void**)&s.ATT, g_ATT);

  // fc1 + relu
  GP p{};
  p = {x,0,Lf, fc1_w,0,Dd, s.h0,0,Dd, Bb*NIN,Dd,Lf, 1,1, fc1_b,0.f,nullptr};
  gemm(CBIG,false,p,1);

  // token rearrangement + cls
  build_H_k<<<dim3(NT,Bb),256>>>(s.h0, cls_tok, s.H);

  // layer 1
  attn_layer(s.H, l1_ng, l1_nb, l1_qkv, l1_ow, l1_ob, l1_rw, s);

  // PPEG: H -> H2
  copyrows_k<<<dim3(11,Bb),256>>>(s.H, s.H2);
  ppeg_k<<<dim3(169 ,Bb),128>>>(s.H, s.H2, 11 , 13, ct_w7 ,ct_b7 ,ct_w5 ,ct_b5 ,ct_w3 ,ct_b3 );
  ppeg_k<<<dim3(6084,Bb),128>>>(s.H, s.H2, 180, 78, pth_w7,pth_b7,pth_w5,pth_b5,pth_w3,pth_b3);

  // layer 2
  attn_layer(s.H2, l2_ng, l2_nb, l2_qkv, l2_ow, l2_ob, l2_rw, s);

  // final layernorm of cls row
  final_ln_k<<<Bb,256>>>(s.H2, norm_g, norm_b, (float*)d_out);
}

// round 2
// speedup vs baseline: 1.7949x; 1.7949x over previous
#include <cuda_runtime.h>
#include <math.h>
#include <stdint.h>

// ---------------- problem constants ----------------
constexpr int Bb   = 4;
constexpr int NIN  = 6170;
constexpr int Lf   = 768;
constexpr int Dd   = 512;
constexpr int NT   = 6264;   // tokens incl cls
constexpr int NP   = 6400;   // padded length for attention
constexpr int PADT = 136;    // front zero-pad
constexpr int HH   = 8;
constexpr int DH   = 64;
constexpr int LM   = 256;    // landmarks
constexpr int LFAC = 25;     // NP / LM
constexpr long long QSZ = (long long)Bb*HH*NP*DH;

// ---------------- device scratch ----------------
__device__ float g_h0 [12636160];
__device__ float g_H  [12828672];
__device__ float g_H2 [12828672];
__device__ float g_XP [13107200];
__device__ float g_QKV[39321600];
__device__ float g_QL [524288];
__device__ float g_KL [524288];
__device__ float g_S1 [52428800];
__device__ float g_S3 [52428800];
__device__ float g_A2 [2097152];
__device__ float g_AZ [2097152];
__device__ float g_T1 [2097152];
__device__ float g_T2 [2097152];
__device__ float g_Za [2097152];
__device__ float g_Zb [2097152];
__device__ float g_RED[64];
__device__ float g_A3V[524288];
__device__ float g_W2 [524288];
__device__ float g_PRT[4194304];
__device__ float g_ATT[13107200];

// ---------------- GEMM params ----------------
struct GP {
  const float* A; long long sA; int lda;
  const float* B; long long sB; int ldb;
  float*       C; long long sC; int ldc;
  int M, N, K, ksplit, epi;
  const float* bias; float alpha; float* out2;
};
// epi: 0=store 1=relu+bias 2=qkv-scatter 3=alpha*I-acc 4=alpha*acc
//      5=attnT-scatter 6=residual+bias add 7=store C and out2=7I-acc

__device__ __forceinline__ uint32_t f2tf(float f){
  uint32_t r; asm("cvt.rna.tf32.f32 %0, %1;" : "=r"(r) : "f"(f)); return r;
}

__device__ __forceinline__ void epi_store(const GP& p, int z, int gm, int gn, float v){
  switch(p.epi){
    case 0:
      p.C[(long long)z*p.sC + (long long)gm*p.ldc + gn] = v; break;
    case 1: {
      v += p.bias[gn];
      p.C[(long long)z*p.sC + (long long)gm*p.ldc + gn] = v>0.f?v:0.f;
    } break;
    case 2: {
      int which = gn >> 9; int hh = (gn >> 6) & 7; int d = gn & 63;
      float s = (which==0) ? p.alpha : 1.f;
      p.out2[(long long)which*QSZ + (((long long)z*HH+hh)*NP + gm)*DH + d] = s*v;
    } break;
    case 3:
      p.C[(long long)z*p.sC + (long long)gm*p.ldc + gn] = (gm==gn?p.alpha:0.f) - v; break;
    case 4:
      p.C[(long long)z*p.sC + (long long)gm*p.ldc + gn] = p.alpha * v; break;
    case 5: {
      int b = z >> 3, hh = z & 7;
      p.out2[((long long)b*NP + (PADT+gm))*Dd + hh*DH + gn] = v;
    } break;
    case 6: {
      long long o = (long long)z*p.sC + (long long)gm*p.ldc + gn;
      p.C[o] += v + p.bias[gn];
    } break;
    case 7: {
      long long o = (long long)z*p.sC + (long long)gm*p.ldc + gn;
      p.C[o] = v;
      p.out2[o] = (gm==gn?7.f:0.f) - v;
    } break;
  }
}

// ---------------- TF32 tensor-core batched GEMM ----------------
template<int BM,int BN,bool TB>
__global__ void __launch_bounds__(256) tgemm_k(GP p){
  constexpr int BK = 16;
  constexpr int WM = BM/4, WN = BN/2;     // warp tile
  constexpr int MT = WM/16, NTt = WN/8;   // mma tiles per warp
  constexpr int SA = BM+8, SB = BN+8;     // padded strides (floats)
  __shared__ uint32_t As[BK*SA];
  __shared__ uint32_t Bs[BK*SB];

  const int tid = threadIdx.x, wid = tid>>5, lane = tid&31;
  const int gid = lane>>2, tig = lane&3;
  const int m0w = (wid>>1)*WM, n0w = (wid&1)*WN;
  const int z  = blockIdx.z;
  const int zb = z / p.ksplit, ks = z % p.ksplit;
  const int klen = p.K / p.ksplit, kb = ks*klen;
  const float* A  = p.A + (long long)zb * p.sA;
  const float* Bm = p.B + (long long)zb * p.sB;
  const int row0 = blockIdx.y * BM, col0 = blockIdx.x * BN;

  float acc[MT][NTt][4];
  #pragma unroll
  for(int i=0;i<MT;i++)
    #pragma unroll
    for(int j=0;j<NTt;j++)
      #pragma unroll
      for(int q=0;q<4;q++) acc[i][j][q]=0.f;

  for(int kt = kb; kt < kb+klen; kt += BK){
    // ---- A tile: [BM x BK] -> As[k][m], float4 along k, tf32 convert ----
    #pragma unroll
    for(int t=0;t<(BM*BK/4)/256;t++){
      int i = tid + t*256;
      int m = i>>2, k = (i&3)*4;
      int gm = row0 + m;
      float4 v = (gm < p.M) ? *(const float4*)(A + (long long)gm*p.lda + kt + k)
                            : make_float4(0.f,0.f,0.f,0.f);
      As[(k+0)*SA + m] = f2tf(v.x);
      As[(k+1)*SA + m] = f2tf(v.y);
      As[(k+2)*SA + m] = f2tf(v.z);
      As[(k+3)*SA + m] = f2tf(v.w);
    }
    // ---- B tile ----
    if (TB){
      #pragma unroll
      for(int t=0;t<(BN*BK/4)/256;t++){
        int i = tid + t*256;
        int n = i>>2, k = (i&3)*4;
        int gn = col0 + n;
        float4 v = *(const float4*)(Bm + (long long)gn*p.ldb + kt + k);
        Bs[(k+0)*SB + n] = f2tf(v.x);
        Bs[(k+1)*SB + n] = f2tf(v.y);
        Bs[(k+2)*SB + n] = f2tf(v.z);
        Bs[(k+3)*SB + n] = f2tf(v.w);
      }
    } else {
      #pragma unroll
      for(int t=0;t<(BN*BK/4)/256;t++){
        int i = tid + t*256;
        int n4 = i % (BN/4), k = i / (BN/4);
        float4 v = *(const float4*)(Bm + (long long)(kt+k)*p.ldb + col0 + 4*n4);
        uint4 u; u.x=f2tf(v.x); u.y=f2tf(v.y); u.z=f2tf(v.z); u.w=f2tf(v.w);
        *(uint4*)&Bs[k*SB + 4*n4] = u;
      }
    }
    __syncthreads();

    #pragma unroll
    for(int kk=0;kk<2;kk++){
      const int k0 = kk*8;
      uint32_t af[MT][4], bf[NTt][2];
      #pragma unroll
      for(int mt=0;mt<MT;mt++){
        int m = m0w + mt*16 + gid;
        af[mt][0] = As[(k0+tig  )*SA + m];
        af[mt][1] = As[(k0+tig  )*SA + m + 8];
        af[mt][2] = As[(k0+tig+4)*SA + m];
        af[mt][3] = As[(k0+tig+4)*SA + m + 8];
      }
      #pragma unroll
      for(int nt=0;nt<NTt;nt++){
        int n = n0w + nt*8 + gid;
        bf[nt][0] = Bs[(k0+tig  )*SB + n];
        bf[nt][1] = Bs[(k0+tig+4)*SB + n];
      }
      #pragma unroll
      for(int mt=0;mt<MT;mt++)
        #pragma unroll
        for(int nt=0;nt<NTt;nt++){
          asm volatile(
            "mma.sync.aligned.m16n8k8.row.col.f32.tf32.tf32.f32 "
            "{%0,%1,%2,%3},{%4,%5,%6,%7},{%8,%9},{%0,%1,%2,%3};"
            : "+f"(acc[mt][nt][0]), "+f"(acc[mt][nt][1]),
              "+f"(acc[mt][nt][2]), "+f"(acc[mt][nt][3])
            : "r"(af[mt][0]), "r"(af[mt][1]), "r"(af[mt][2]), "r"(af[mt][3]),
              "r"(bf[nt][0]), "r"(bf[nt][1]));
        }
    }
    __syncthreads();
  }

  // ---- epilogue ----
  #pragma unroll
  for(int mt=0;mt<MT;mt++){
    int r = row0 + m0w + mt*16 + gid;
    #pragma unroll
    for(int nt=0;nt<NTt;nt++){
      int c = col0 + n0w + nt*8 + tig*2;
      if (r < p.M){
        epi_store(p, z, r, c,   acc[mt][nt][0]);
        epi_store(p, z, r, c+1, acc[mt][nt][1]);
      }
      if (r+8 < p.M){
        epi_store(p, z, r+8, c,   acc[mt][nt][2]);
        epi_store(p, z, r+8, c+1, acc[mt][nt][3]);
      }
    }
  }
}

// ---------------- small kernels ----------------
__global__ void build_H_k(const float* __restrict__ h0, const float* __restrict__ cls,
                          float* __restrict__ Hb){
  int t = blockIdx.x, b = blockIdx.y;
  int src;
  if (t == 0) src = -1;
  else if (t <= 10) src = t-1;
  else if (t < 180){ int j=t-11; src = 10 + (j<160 ? j : j-160); }
  else             { int j=t-180; src = 170 + (j<6000 ? j : j-6000); }
  const float* s = (src<0) ? cls : h0 + ((long long)b*NIN + src)*Dd;
  float* d = Hb + ((long long)b*NT + t)*Dd;
  for(int c=threadIdx.x;c<Dd;c+=256) d[c]=s[c];
}

__global__ void ln_pad_k(const float* __restrict__ Hin, const float* __restrict__ g,
                         const float* __restrict__ bb, float* __restrict__ XP){
  __shared__ float red[256];
  int n = blockIdx.x, b = blockIdx.y, t = threadIdx.x;
  float* out = XP + ((long long)b*NP + n)*Dd;
  if (n < PADT){ out[t]=0.f; out[t+256]=0.f; return; }
  const float* x = Hin + ((long long)b*NT + (n-PADT))*Dd;
  float v0=x[t], v1=x[t+256];
  red[t]=v0+v1; __syncthreads();
  for(int o=128;o>0;o>>=1){ if(t<o) red[t]+=red[t+o]; __syncthreads(); }
  float mu = red[0]*(1.f/512.f); __syncthreads();
  float d0=v0-mu, d1=v1-mu;
  red[t]=d0*d0+d1*d1; __syncthreads();
  for(int o=128;o>0;o>>=1){ if(t<o) red[t]+=red[t+o]; __syncthreads(); }
  float rs = rsqrtf(red[0]*(1.f/512.f)+1e-5f);
  out[t]     = d0*rs*g[t]     + bb[t];
  out[t+256] = d1*rs*g[t+256] + bb[t+256];
}

__global__ void landmarks_k(const float* __restrict__ Q, const float* __restrict__ K,
                            float* __restrict__ QL, float* __restrict__ KL){
  int idx = blockIdx.x*256 + threadIdx.x;
  int d = idx & 63; int i = (idx>>6) & 255; int bh = idx >> 14;
  long long base = ((long long)bh*NP + (long long)i*LFAC)*DH + d;
  float sq=0.f, sk=0.f;
  #pragma unroll
  for(int j=0;j<LFAC;j++){ sq += Q[base + (long long)j*DH]; sk += K[base + (long long)j*DH]; }
  QL[idx] = sq*(1.f/LFAC); KL[idx] = sk*(1.f/LFAC);
}

__global__ void softmax_k(float* __restrict__ x, long long bstride, int n){
  __shared__ float red[256];
  float* row = x + (long long)blockIdx.y*bstride + (long long)blockIdx.x*n;
  int t = threadIdx.x;
  float mx = -3.4e38f;
  for(int i=t;i<n;i+=256) mx = fmaxf(mx, row[i]);
  red[t]=mx; __syncthreads();
  for(int o=128;o>0;o>>=1){ if(t<o) red[t]=fmaxf(red[t],red[t+o]); __syncthreads(); }
  mx = red[0]; __syncthreads();
  float s=0.f;
  for(int i=t;i<n;i+=256){ float e=expf(row[i]-mx); row[i]=e; s+=e; }
  red[t]=s; __syncthreads();
  for(int o=128;o>0;o>>=1){ if(t<o) red[t]+=red[t+o]; __syncthreads(); }
  float inv = 1.f/red[0];
  for(int i=t;i<n;i+=256) row[i]*=inv;
}

__global__ void pinv_part_k(const float* __restrict__ A, float* __restrict__ red){
  __shared__ float s1[256], s2[256];
  int bh = blockIdx.x, t = threadIdx.x;
  const float* a = A + (long long)bh*65536;
  float rs=0.f, cs=0.f;
  for(int c=0;c<256;c++) rs += fabsf(a[t*256+c]);
  for(int r=0;r<256;r++) cs += fabsf(a[r*256+t]);
  s1[t]=rs; s2[t]=cs; __syncthreads();
  for(int o=128;o>0;o>>=1){ if(t<o){ s1[t]=fmaxf(s1[t],s1[t+o]); s2[t]=fmaxf(s2[t],s2[t+o]); } __syncthreads(); }
  if(t==0){ red[bh]=s1[0]; red[32+bh]=s2[0]; }
}

__global__ void pinv_trans_k(const float* __restrict__ A, const float* __restrict__ red,
                             float* __restrict__ Z){
  int bh = blockIdx.x, t = threadIdx.x;
  float col=0.f, row=0.f;
  for(int i=0;i<32;i++){ col=fmaxf(col,red[i]); row=fmaxf(row,red[32+i]); }
  float inv = 1.f/(col*row);
  const float* a = A + (long long)bh*65536;
  float* z = Z + (long long)bh*65536;
  for(int i=0;i<256;i++) z[i*256+t] = a[t*256+i]*inv;
}

__global__ void reduce8_k(const float* __restrict__ P, float* __restrict__ O){
  long long i = (long long)blockIdx.x*256 + threadIdx.x;
  int zb = (int)(i>>14); int e = (int)(i & 16383);
  float s=0.f;
  #pragma unroll
  for(int k=0;k<8;k++) s += P[(((long long)zb*8+k)<<14) + e];
  O[i]=s;
}

__global__ void dwconv_k(const float* __restrict__ V, const float* __restrict__ w,
                         float* __restrict__ att){
  int bh = blockIdx.y; int b = bh>>3, h = bh&7;
  int lt = threadIdx.x; int sub = lt>>6; int d = lt&63;
  int n = PADT + blockIdx.x*4 + sub;
  const float* vb = V + (long long)bh*NP*DH;
  const float* wh = w + h*33;
  float acc=0.f;
  #pragma unroll
  for(int t=0;t<33;t++){
    int nn = n + t - 16;
    if(nn>=0 && nn<NP) acc += vb[(long long)nn*DH + d]*wh[t];
  }
  att[((long long)b*NP + n)*Dd + h*DH + d] += acc;
}

__global__ void copyrows_k(const float* __restrict__ Hin, float* __restrict__ Hout){
  int t = blockIdx.x, b = blockIdx.y;
  long long o = ((long long)b*NT + t)*Dd;
  Hout[o+threadIdx.x]     = Hin[o+threadIdx.x];
  Hout[o+threadIdx.x+256] = Hin[o+threadIdx.x+256];
}

__global__ void ppeg_k(const float* __restrict__ Hin, float* __restrict__ Hout,
                       int tok0, int S,
                       const float* __restrict__ w7, const float* __restrict__ b7,
                       const float* __restrict__ w5, const float* __restrict__ b5,
                       const float* __restrict__ w3, const float* __restrict__ b3){
  int p = blockIdx.x, b = blockIdx.y;
  int y = p / S, x = p % S;
  const float* base = Hin + ((long long)b*NT + tok0)*Dd;
  float* out = Hout + ((long long)b*NT + tok0 + p)*Dd;
  for(int c=threadIdx.x;c<Dd;c+=blockDim.x){
    float acc = base[(long long)p*Dd + c] + b7[c] + b5[c] + b3[c];
    const float* wc7 = w7 + c*49;
    const float* wc5 = w5 + c*25;
    const float* wc3 = w3 + c*9;
    #pragma unroll
    for(int ky=0;ky<7;ky++){
      int yy=y+ky-3; if(yy<0||yy>=S) continue;
      #pragma unroll
      for(int kx=0;kx<7;kx++){
        int xx=x+kx-3; if(xx<0||xx>=S) continue;
        acc += base[(long long)(yy*S+xx)*Dd + c]*wc7[ky*7+kx];
      }
    }
    #pragma unroll
    for(int ky=0;ky<5;ky++){
      int yy=y+ky-2; if(yy<0||yy>=S) continue;
      #pragma unroll
      for(int kx=0;kx<5;kx++){
        int xx=x+kx-2; if(xx<0||xx>=S) continue;
        acc += base[(long long)(yy*S+xx)*Dd + c]*wc5[ky*5+kx];
      }
    }
    #pragma unroll
    for(int ky=0;ky<3;ky++){
      int yy=y+ky-1; if(yy<0||yy>=S) continue;
      #pragma unroll
      for(int kx=0;kx<3;kx++){
        int xx=x+kx-1; if(xx<0||xx>=S) continue;
        acc += base[(long long)(yy*S+xx)*Dd + c]*wc3[ky*3+kx];
      }
    }
    out[c]=acc;
  }
}

__global__ void final_ln_k(const float* __restrict__ Hb, const float* __restrict__ g,
                           const float* __restrict__ bb, float* __restrict__ out){
  __shared__ float red[256];
  int b = blockIdx.x, t = threadIdx.x;
  const float* x = Hb + (long long)b*NT*Dd;
  float v0=x[t], v1=x[t+256];
  red[t]=v0+v1; __syncthreads();
  for(int o=128;o>0;o>>=1){ if(t<o) red[t]+=red[t+o]; __syncthreads(); }
  float mu = red[0]*(1.f/512.f); __syncthreads();
  float d0=v0-mu, d1=v1-mu;
  red[t]=d0*d0+d1*d1; __syncthreads();
  for(int o=128;o>0;o>>=1){ if(t<o) red[t]+=red[t+o]; __syncthreads(); }
  float rs = rsqrtf(red[0]*(1.f/512.f)+1e-5f);
  out[b*Dd + t]     = d0*rs*g[t]     + bb[t];
  out[b*Dd + t+256] = d1*rs*g[t+256] + bb[t+256];
}

// ---------------- host side ----------------
static void tgemm(bool big, bool tb, GP p, int batches){
  int BN = big ? 128 : 64;
  dim3 g(p.N / BN, (p.M + 127)/128, batches * p.ksplit);
  if (big){
    if (tb) tgemm_k<128,128,true ><<<g,256>>>(p);
    else    tgemm_k<128,128,false><<<g,256>>>(p);
  } else {
    if (tb) tgemm_k<128,64,true ><<<g,256>>>(p);
    else    tgemm_k<128,64,false><<<g,256>>>(p);
  }
}

struct Scratch {
  float *h0,*H,*H2,*XP,*QKV,*QL,*KL,*S1,*S3,*A2,*AZ,*T1,*T2,*Za,*Zb,*RED,*A3V,*W2,*PRT,*ATT;
};

static void attn_layer(float* Hbuf, const float* ng, const float* nb,
                       const float* qkvw, const float* ow, const float* ob,
                       const float* rw, const Scratch& s){
  float* Q  = s.QKV;
  float* Kp = s.QKV + QSZ;
  float* V  = s.QKV + 2*QSZ;
  GP p{};

  ln_pad_k<<<dim3(NP,Bb),256>>>(Hbuf, ng, nb, s.XP);

  // QKV projection + head scatter
  p = {s.XP,(long long)NP*Dd,Dd, qkvw,0,3*Dd, nullptr,0,0, NP,3*Dd,Dd, 1,2, nullptr,0.125f, s.QKV};
  tgemm(true,false,p,Bb);

  landmarks_k<<<2048,256>>>(Q, Kp, s.QL, s.KL);

  // sim2 = QL @ KL^T
  p = {s.QL,(long long)LM*DH,DH, s.KL,(long long)LM*DH,DH, s.A2,(long long)LM*LM,LM, LM,LM,DH,1,0,nullptr,0.f,nullptr};
  tgemm(true,true,p,32);
  softmax_k<<<dim3(LM,32),256>>>(s.A2,(long long)LM*LM,LM);

  // pinv init
  pinv_part_k<<<32,256>>>(s.A2, s.RED);
  pinv_trans_k<<<32,256>>>(s.A2, s.RED, s.Za);
  float* zc = s.Za; float* zn = s.Zb;
  for(int it=0;it<6;it++){
    // AZ = a2 @ z   and  T1 = 7I - AZ (fused epilogue)
    p = {s.A2,65536,LM, zc,65536,LM, s.AZ,65536,LM, LM,LM,LM,1,7,nullptr,0.f,s.T1};
    tgemm(true,false,p,32);
    p = {s.AZ,65536,LM, s.T1,65536,LM, s.T2,65536,LM, LM,LM,LM,1,3,nullptr,15.f,nullptr};
    tgemm(true,false,p,32);
    p = {s.AZ,65536,LM, s.T2,65536,LM, s.T1,65536,LM, LM,LM,LM,1,3,nullptr,13.f,nullptr};
    tgemm(true,false,p,32);
    p = {zc,65536,LM, s.T1,65536,LM, zn,65536,LM, LM,LM,LM,1,4,nullptr,0.25f,nullptr};
    tgemm(true,false,p,32);
    float* t=zc; zc=zn; zn=t;
  }

  // sim1 = q @ KL^T (valid tokens only)
  p = {Q+(long long)PADT*DH,(long long)NP*DH,DH, s.KL,(long long)LM*DH,DH,
       s.S1+(long long)PADT*LM,(long long)NP*LM,LM, NT,LM,DH,1,0,nullptr,0.f,nullptr};
  tgemm(true,true,p,32);
  softmax_k<<<dim3(NT,32),256>>>(s.S1+(long long)PADT*LM,(long long)NP*LM,LM);

  // sim3 = QL @ K^T
  p = {s.QL,(long long)LM*DH,DH, Kp,(long long)NP*DH,DH, s.S3,(long long)LM*NP,NP, LM,NP,DH,1,0,nullptr,0.f,nullptr};
  tgemm(true,true,p,32);
  softmax_k<<<dim3(LM,32),256>>>(s.S3,(long long)LM*NP,NP);

  // a3v = a3 @ v (split-K 8)
  p = {s.S3,(long long)LM*NP,NP, V,(long long)NP*DH,DH, s.PRT,(long long)LM*DH,DH, LM,DH,NP,8,0,nullptr,0.f,nullptr};
  tgemm(false,false,p,32);
  reduce8_k<<<2048,256>>>(s.PRT, s.A3V);

  // w2 = Z @ a3v
  p = {zc,65536,LM, s.A3V,(long long)LM*DH,DH, s.W2,(long long)LM*DH,DH, LM,DH,LM,1,0,nullptr,0.f,nullptr};
  tgemm(false,false,p,32);

  // attn = a1 @ w2 -> token-major scatter
  p = {s.S1+(long long)PADT*LM,(long long)NP*LM,LM, s.W2,(long long)LM*DH,DH, nullptr,0,0,
       NT,DH,LM,1,5,nullptr,0.f,s.ATT};
  tgemm(false,false,p,32);

  dwconv_k<<<dim3(1566,32),256>>>(V, rw, s.ATT);

  // out proj + residual add
  p = {s.ATT+(long long)PADT*Dd,(long long)NP*Dd,Dd, ow,0,Dd, Hbuf,(long long)NT*Dd,Dd,
       NT,Dd,Dd,1,6,ob,0.f,nullptr};
  tgemm(true,false,p,Bb);
}

extern "C" void kernel_launch(void* const* d_in, const int* in_sizes, int n_in,
                              void* d_out, int out_size){
  const float* x        = (const float*)d_in[0];
  const float* fc1_w    = (const float*)d_in[1];
  const float* fc1_b    = (const float*)d_in[2];
  const float* cls_tok  = (const float*)d_in[3];
  const float* l1_ng    = (const float*)d_in[4];
  const float* l1_nb    = (const float*)d_in[5];
  const float* l1_qkv   = (const float*)d_in[6];
  const float* l1_ow    = (const float*)d_in[7];
  const float* l1_ob    = (const float*)d_in[8];
  const float* l1_rw    = (const float*)d_in[9];
  const float* ct_w7    = (const float*)d_in[10];
  const float* ct_b7    = (const float*)d_in[11];
  const float* ct_w5    = (const float*)d_in[12];
  const float* ct_b5    = (const float*)d_in[13];
  const float* ct_w3    = (const float*)d_in[14];
  const float* ct_b3    = (const float*)d_in[15];
  const float* pth_w7   = (const float*)d_in[16];
  const float* pth_b7   = (const float*)d_in[17];
  const float* pth_w5   = (const float*)d_in[18];
  const float* pth_b5   = (const float*)d_in[19];
  const float* pth_w3   = (const float*)d_in[20];
  const float* pth_b3   = (const float*)d_in[21];
  const float* l2_ng    = (const float*)d_in[22];
  const float* l2_nb    = (const float*)d_in[23];
  const float* l2_qkv   = (const float*)d_in[24];
  const float* l2_ow    = (const float*)d_in[25];
  const float* l2_ob    = (const float*)d_in[26];
  const float* l2_rw    = (const float*)d_in[27];
  const float* norm_g   = (const float*)d_in[28];
  const float* norm_b   = (const float*)d_in[29];

  Scratch s;
  cudaGetSymbolAddress((void**)&s.h0 , g_h0 );
  cudaGetSymbolAddress((void**)&s.H  , g_H  );
  cudaGetSymbolAddress((void**)&s.H2 , g_H2 );
  cudaGetSymbolAddress((void**)&s.XP , g_XP );
  cudaGetSymbolAddress((void**)&s.QKV, g_QKV);
  cudaGetSymbolAddress((void**)&s.QL , g_QL );
  cudaGetSymbolAddress((void**)&s.KL , g_KL );
  cudaGetSymbolAddress((void**)&s.S1 , g_S1 );
  cudaGetSymbolAddress((void**)&s.S3 , g_S3 );
  cudaGetSymbolAddress((void**)&s.A2 , g_A2 );
  cudaGetSymbolAddress((void**)&s.AZ , g_AZ );
  cudaGetSymbolAddress((void**)&s.T1 , g_T1 );
  cudaGetSymbolAddress((void**)&s.T2 , g_T2 );
  cudaGetSymbolAddress((void**)&s.Za , g_Za );
  cudaGetSymbolAddress((void**)&s.Zb , g_Zb );
  cudaGetSymbolAddress((void**)&s.RED, g_RED);
  cudaGetSymbolAddress((void**)&s.A3V, g_A3V);
  cudaGetSymbolAddress((void**)&s.W2 , g_W2 );
  cudaGetSymbolAddress((void**)&s.PRT, g_PRT);
  cudaGetSymbolAddress((void**)&s.ATT, g_ATT);

  GP p{};
  // fc1 + relu
  p = {x,0,Lf, fc1_w,0,Dd, s.h0,0,Dd, Bb*NIN,Dd,Lf, 1,1, fc1_b,0.f,nullptr};
  tgemm(true,false,p,1);

  build_H_k<<<dim3(NT,Bb),256>>>(s.h0, cls_tok, s.H);

  attn_layer(s.H, l1_ng, l1_nb, l1_qkv, l1_ow, l1_ob, l1_rw, s);

  copyrows_k<<<dim3(11,Bb),256>>>(s.H, s.H2);
  ppeg_k<<<dim3(169 ,Bb),128>>>(s.H, s.H2, 11 , 13, ct_w7 ,ct_b7 ,ct_w5 ,ct_b5 ,ct_w3 ,ct_b3 );
  ppeg_k<<<dim3(6084,Bb),128>>>(s.H, s.H2, 180, 78, pth_w7,pth_b7,pth_w5,pth_b5,pth_w3,pth_b3);

  attn_layer(s.H2, l2_ng, l2_nb, l2_qkv, l2_ow, l2_ob, l2_rw, s);

  final_ln_k<<<Bb,256>>>(s.H2, norm_g, norm_b, (float*)d_out);
}

// round 3
// speedup vs baseline: 1.8873x; 1.0515x over previous
#include <cuda_runtime.h>
#include <math.h>
#include <stdint.h>

// ---------------- problem constants ----------------
constexpr int Bb   = 4;
constexpr int NIN  = 6170;
constexpr int Lf   = 768;
constexpr int Dd   = 512;
constexpr int NT   = 6264;   // tokens incl cls
constexpr int NP   = 6400;   // padded length for attention
constexpr int PADT = 136;    // front zero-pad
constexpr int HH   = 8;
constexpr int DH   = 64;
constexpr int LM   = 256;    // landmarks
constexpr int LFAC = 25;     // NP / LM
constexpr long long QSZ = (long long)Bb*HH*NP*DH;

// ---------------- device scratch ----------------
__device__ float g_h0 [12636160];
__device__ float g_H  [12828672];
__device__ float g_H2 [12828672];
__device__ float g_XP [13107200];
__device__ float g_QKV[39321600];
__device__ float g_QL [524288];
__device__ float g_KL [524288];
__device__ float g_S1 [52428800];
__device__ float g_S3 [52428800];
__device__ float g_A2 [2097152];
__device__ float g_AZ [2097152];
__device__ float g_T1 [2097152];
__device__ float g_T2 [2097152];
__device__ float g_Za [2097152];
__device__ float g_Zb [2097152];
__device__ float g_RED[64];
__device__ float g_A3V[524288];
__device__ float g_W2 [524288];
__device__ float g_PRT[4194304];
__device__ float g_ATT[13107200];

// ---------------- GEMM params ----------------
struct GP {
  const float* A; long long sA; int lda;
  const float* B; long long sB; int ldb;
  float*       C; long long sC; int ldc;
  int M, N, K, ksplit, epi;
  const float* bias; float alpha; float* out2;
};
// epi: 0=store 1=relu+bias 2=qkv-scatter 3=alpha*I-acc 4=alpha*acc
//      5=attnT-scatter 6=residual+bias add 7=store C and out2=7I-acc

__device__ __forceinline__ void epi_store(const GP& p, int z, int gm, int gn, float v){
  switch(p.epi){
    case 0:
      p.C[(long long)z*p.sC + (long long)gm*p.ldc + gn] = v; break;
    case 1: {
      v += p.bias[gn];
      p.C[(long long)z*p.sC + (long long)gm*p.ldc + gn] = v>0.f?v:0.f;
    } break;
    case 2: {
      int which = gn >> 9; int hh = (gn >> 6) & 7; int d = gn & 63;
      float s = (which==0) ? p.alpha : 1.f;
      p.out2[(long long)which*QSZ + (((long long)z*HH+hh)*NP + gm)*DH + d] = s*v;
    } break;
    case 3:
      p.C[(long long)z*p.sC + (long long)gm*p.ldc + gn] = (gm==gn?p.alpha:0.f) - v; break;
    case 4:
      p.C[(long long)z*p.sC + (long long)gm*p.ldc + gn] = p.alpha * v; break;
    case 5: {
      int b = z >> 3, hh = z & 7;
      p.out2[((long long)b*NP + (PADT+gm))*Dd + hh*DH + gn] = v;
    } break;
    case 6: {
      long long o = (long long)z*p.sC + (long long)gm*p.ldc + gn;
      p.C[o] += v + p.bias[gn];
    } break;
    case 7: {
      long long o = (long long)z*p.sC + (long long)gm*p.ldc + gn;
      p.C[o] = v;
      p.out2[o] = (gm==gn?7.f:0.f) - v;
    } break;
  }
}

// ---------------- cp.async helpers ----------------
__device__ __forceinline__ void cpa16(uint32_t* smem, const float* g, bool pred){
  uint32_t s = (uint32_t)__cvta_generic_to_shared(smem);
  int sz = pred ? 16 : 0;
  asm volatile("cp.async.cg.shared.global [%0],[%1],16,%2;" :: "r"(s), "l"(g), "r"(sz));
}
__device__ __forceinline__ void cp_commit(){ asm volatile("cp.async.commit_group;"); }
__device__ __forceinline__ void cp_wait0 (){ asm volatile("cp.async.wait_group 0;"); }

// ---------------- TF32 tensor-core batched GEMM (cp.async double-buffered) ----------------
template<int BM,int BN,int WM,int WN,bool TB>
__global__ void __launch_bounds__(256,2) tgemm_k(GP p){
  constexpr int BK  = 16;
  constexpr int SAK = BK + 4;              // padded k-stride (words)
  constexpr int SBN = BN + 4;              // padded n-stride (non-TB)
  constexpr int WC  = BN / WN;             // warp cols
  constexpr int MT  = WM / 16, NTt = WN / 8;
  static_assert((BM/WM)*(BN/WN) == 8, "8 warps");
  __shared__ uint32_t As[2][BM*SAK];
  __shared__ uint32_t Bs[2][TB ? BN*SAK : BK*SBN];

  const int tid = threadIdx.x, wid = tid>>5, lane = tid&31;
  const int gid = lane>>2, tig = lane&3;
  const int m0w = (wid / WC) * WM, n0w = (wid % WC) * WN;
  const int z  = blockIdx.z;
  const int zb = z / p.ksplit, ks = z % p.ksplit;
  const int klen = p.K / p.ksplit, kb = ks*klen;
  const float* A  = p.A + (long long)zb * p.sA;
  const float* Bm = p.B + (long long)zb * p.sB;
  const int row0 = blockIdx.y * BM, col0 = blockIdx.x * BN;

  auto loadA = [&](int stg, int kt){
    #pragma unroll
    for(int t=0;t<BM/64;t++){
      int i = tid + t*256;
      int m = i>>2, kc = (i&3)*4;
      int gm = row0 + m;
      cpa16(&As[stg][m*SAK + kc], A + (long long)gm*p.lda + kt + kc, gm < p.M);
    }
  };
  auto loadB = [&](int stg, int kt){
    if (TB){
      #pragma unroll
      for(int t=0;t<BN/64;t++){
        int i = tid + t*256;
        int n = i>>2, kc = (i&3)*4;
        cpa16(&Bs[stg][n*SAK + kc], Bm + (long long)(col0+n)*p.ldb + kt + kc, true);
      }
    } else {
      #pragma unroll
      for(int t=0;t<(BK*BN/4)/256;t++){
        int i = tid + t*256;
        int n4 = i % (BN/4), k = i / (BN/4);
        cpa16(&Bs[stg][k*SBN + 4*n4], Bm + (long long)(kt+k)*p.ldb + col0 + 4*n4, true);
      }
    }
  };

  float acc[MT][NTt][4];
  #pragma unroll
  for(int i=0;i<MT;i++)
    #pragma unroll
    for(int j=0;j<NTt;j++)
      #pragma unroll
      for(int q=0;q<4;q++) acc[i][j][q]=0.f;

  const int ntiles = klen / BK;
  loadA(0, kb); loadB(0, kb); cp_commit();

  for(int it=0; it<ntiles; ++it){
    cp_wait0(); __syncthreads();
    const int stg = it & 1;
    if (it+1 < ntiles){
      loadA(stg^1, kb + (it+1)*BK);
      loadB(stg^1, kb + (it+1)*BK);
      cp_commit();
    }
    #pragma unroll
    for(int kk=0;kk<2;kk++){
      const int k0 = kk*8;
      uint32_t af[MT][4], bf[NTt][2];
      #pragma unroll
      for(int mt=0;mt<MT;mt++){
        int m = m0w + mt*16 + gid;
        af[mt][0] = As[stg][(m  )*SAK + k0 + tig];
        af[mt][1] = As[stg][(m+8)*SAK + k0 + tig];
        af[mt][2] = As[stg][(m  )*SAK + k0 + tig + 4];
        af[mt][3] = As[stg][(m+8)*SAK + k0 + tig + 4];
      }
      #pragma unroll
      for(int nt=0;nt<NTt;nt++){
        int n = n0w + nt*8 + gid;
        if (TB){
          bf[nt][0] = Bs[stg][n*SAK + k0 + tig];
          bf[nt][1] = Bs[stg][n*SAK + k0 + tig + 4];
        } else {
          bf[nt][0] = Bs[stg][(k0+tig  )*SBN + n];
          bf[nt][1] = Bs[stg][(k0+tig+4)*SBN + n];
        }
      }
      #pragma unroll
      for(int mt=0;mt<MT;mt++)
        #pragma unroll
        for(int nt=0;nt<NTt;nt++){
          asm volatile(
            "mma.sync.aligned.m16n8k8.row.col.f32.tf32.tf32.f32 "
            "{%0,%1,%2,%3},{%4,%5,%6,%7},{%8,%9},{%0,%1,%2,%3};"
            : "+f"(acc[mt][nt][0]), "+f"(acc[mt][nt][1]),
              "+f"(acc[mt][nt][2]), "+f"(acc[mt][nt][3])
            : "r"(af[mt][0]), "r"(af[mt][1]), "r"(af[mt][2]), "r"(af[mt][3]),
              "r"(bf[nt][0]), "r"(bf[nt][1]));
        }
    }
    __syncthreads();
  }

  #pragma unroll
  for(int mt=0;mt<MT;mt++){
    int r = row0 + m0w + mt*16 + gid;
    #pragma unroll
    for(int nt=0;nt<NTt;nt++){
      int c = col0 + n0w + nt*8 + tig*2;
      if (r < p.M){
        epi_store(p, z, r, c,   acc[mt][nt][0]);
        epi_store(p, z, r, c+1, acc[mt][nt][1]);
      }
      if (r+8 < p.M){
        epi_store(p, z, r+8, c,   acc[mt][nt][2]);
        epi_store(p, z, r+8, c+1, acc[mt][nt][3]);
      }
    }
  }
}

// ---------------- small kernels ----------------
__global__ void build_H_k(const float* __restrict__ h0, const float* __restrict__ cls,
                          float* __restrict__ Hb){
  int t = blockIdx.x, b = blockIdx.y;
  int src;
  if (t == 0) src = -1;
  else if (t <= 10) src = t-1;
  else if (t < 180){ int j=t-11; src = 10 + (j<160 ? j : j-160); }
  else             { int j=t-180; src = 170 + (j<6000 ? j : j-6000); }
  const float* s = (src<0) ? cls : h0 + ((long long)b*NIN + src)*Dd;
  float* d = Hb + ((long long)b*NT + t)*Dd;
  for(int c=threadIdx.x;c<Dd;c+=256) d[c]=s[c];
}

__global__ void ln_pad_k(const float* __restrict__ Hin, const float* __restrict__ g,
                         const float* __restrict__ bb, float* __restrict__ XP){
  __shared__ float red[256];
  int n = blockIdx.x, b = blockIdx.y, t = threadIdx.x;
  float* out = XP + ((long long)b*NP + n)*Dd;
  if (n < PADT){ out[t]=0.f; out[t+256]=0.f; return; }
  const float* x = Hin + ((long long)b*NT + (n-PADT))*Dd;
  float v0=x[t], v1=x[t+256];
  red[t]=v0+v1; __syncthreads();
  for(int o=128;o>0;o>>=1){ if(t<o) red[t]+=red[t+o]; __syncthreads(); }
  float mu = red[0]*(1.f/512.f); __syncthreads();
  float d0=v0-mu, d1=v1-mu;
  red[t]=d0*d0+d1*d1; __syncthreads();
  for(int o=128;o>0;o>>=1){ if(t<o) red[t]+=red[t+o]; __syncthreads(); }
  float rs = rsqrtf(red[0]*(1.f/512.f)+1e-5f);
  out[t]     = d0*rs*g[t]     + bb[t];
  out[t+256] = d1*rs*g[t+256] + bb[t+256];
}

__global__ void landmarks_k(const float* __restrict__ Q, const float* __restrict__ K,
                            float* __restrict__ QL, float* __restrict__ KL){
  int idx = blockIdx.x*256 + threadIdx.x;
  int d = idx & 63; int i = (idx>>6) & 255; int bh = idx >> 14;
  long long base = ((long long)bh*NP + (long long)i*LFAC)*DH + d;
  float sq=0.f, sk=0.f;
  #pragma unroll
  for(int j=0;j<LFAC;j++){ sq += Q[base + (long long)j*DH]; sk += K[base + (long long)j*DH]; }
  QL[idx] = sq*(1.f/LFAC); KL[idx] = sk*(1.f/LFAC);
}

// single-read softmax: row resident in registers
template<int NPT>
__global__ void softmax1_k(float* __restrict__ x, long long bstride, int n){
  __shared__ float red[256];
  float* row = x + (long long)blockIdx.y*bstride + (long long)blockIdx.x*n;
  int t = threadIdx.x;
  float v[NPT];
  float mx = -3.4e38f;
  #pragma unroll
  for(int j=0;j<NPT;j++){
    int i = t + j*256;
    v[j] = row[i];
    mx = fmaxf(mx, v[j]);
  }
  red[t]=mx; __syncthreads();
  for(int o=128;o>0;o>>=1){ if(t<o) red[t]=fmaxf(red[t],red[t+o]); __syncthreads(); }
  mx = red[0]; __syncthreads();
  float s=0.f;
  #pragma unroll
  for(int j=0;j<NPT;j++){ v[j]=__expf(v[j]-mx); s+=v[j]; }
  red[t]=s; __syncthreads();
  for(int o=128;o>0;o>>=1){ if(t<o) red[t]+=red[t+o]; __syncthreads(); }
  float inv = 1.f/red[0];
  #pragma unroll
  for(int j=0;j<NPT;j++){ int i=t+j*256; row[i]=v[j]*inv; }
}

__global__ void pinv_part_k(const float* __restrict__ A, float* __restrict__ red){
  __shared__ float s1[256], s2[256];
  int bh = blockIdx.x, t = threadIdx.x;
  const float* a = A + (long long)bh*65536;
  float rs=0.f, cs=0.f;
  for(int c=0;c<256;c++) rs += fabsf(a[t*256+c]);
  for(int r=0;r<256;r++) cs += fabsf(a[r*256+t]);
  s1[t]=rs; s2[t]=cs; __syncthreads();
  for(int o=128;o>0;o>>=1){ if(t<o){ s1[t]=fmaxf(s1[t],s1[t+o]); s2[t]=fmaxf(s2[t],s2[t+o]); } __syncthreads(); }
  if(t==0){ red[bh]=s1[0]; red[32+bh]=s2[0]; }
}

__global__ void pinv_trans_k(const float* __restrict__ A, const float* __restrict__ red,
                             float* __restrict__ Z){
  int bh = blockIdx.x, t = threadIdx.x;
  float col=0.f, row=0.f;
  for(int i=0;i<32;i++){ col=fmaxf(col,red[i]); row=fmaxf(row,red[32+i]); }
  float inv = 1.f/(col*row);
  const float* a = A + (long long)bh*65536;
  float* z = Z + (long long)bh*65536;
  for(int i=0;i<256;i++) z[i*256+t] = a[t*256+i]*inv;
}

__global__ void reduce8_k(const float* __restrict__ P, float* __restrict__ O){
  long long i = (long long)blockIdx.x*256 + threadIdx.x;
  int zb = (int)(i>>14); int e = (int)(i & 16383);
  float s=0.f;
  #pragma unroll
  for(int k=0;k<8;k++) s += P[(((long long)zb*8+k)<<14) + e];
  O[i]=s;
}

__global__ void dwconv_k(const float* __restrict__ V, const float* __restrict__ w,
                         float* __restrict__ att){
  int bh = blockIdx.y; int b = bh>>3, h = bh&7;
  int lt = threadIdx.x; int sub = lt>>6; int d = lt&63;
  int n = PADT + blockIdx.x*4 + sub;
  const float* vb = V + (long long)bh*NP*DH;
  const float* wh = w + h*33;
  float acc=0.f;
  #pragma unroll
  for(int t=0;t<33;t++){
    int nn = n + t - 16;
    if(nn>=0 && nn<NP) acc += vb[(long long)nn*DH + d]*wh[t];
  }
  att[((long long)b*NP + n)*Dd + h*DH + d] += acc;
}

__global__ void copyrows_k(const float* __restrict__ Hin, float* __restrict__ Hout){
  int t = blockIdx.x, b = blockIdx.y;
  long long o = ((long long)b*NT + t)*Dd;
  Hout[o+threadIdx.x]     = Hin[o+threadIdx.x];
  Hout[o+threadIdx.x+256] = Hin[o+threadIdx.x+256];
}

__global__ void ppeg_k(const float* __restrict__ Hin, float* __restrict__ Hout,
                       int tok0, int S,
                       const float* __restrict__ w7, const float* __restrict__ b7,
                       const float* __restrict__ w5, const float* __restrict__ b5,
                       const float* __restrict__ w3, const float* __restrict__ b3){
  int p = blockIdx.x, b = blockIdx.y;
  int y = p / S, x = p % S;
  const float* base = Hin + ((long long)b*NT + tok0)*Dd;
  float* out = Hout + ((long long)b*NT + tok0 + p)*Dd;
  for(int c=threadIdx.x;c<Dd;c+=blockDim.x){
    float acc = base[(long long)p*Dd + c] + b7[c] + b5[c] + b3[c];
    const float* wc7 = w7 + c*49;
    const float* wc5 = w5 + c*25;
    const float* wc3 = w3 + c*9;
    #pragma unroll
    for(int ky=0;ky<7;ky++){
      int yy=y+ky-3; if(yy<0||yy>=S) continue;
      #pragma unroll
      for(int kx=0;kx<7;kx++){
        int xx=x+kx-3; if(xx<0||xx>=S) continue;
        acc += base[(long long)(yy*S+xx)*Dd + c]*wc7[ky*7+kx];
      }
    }
    #pragma unroll
    for(int ky=0;ky<5;ky++){
      int yy=y+ky-2; if(yy<0||yy>=S) continue;
      #pragma unroll
      for(int kx=0;kx<5;kx++){
        int xx=x+kx-2; if(xx<0||xx>=S) continue;
        acc += base[(long long)(yy*S+xx)*Dd + c]*wc5[ky*5+kx];
      }
    }
    #pragma unroll
    for(int ky=0;ky<3;ky++){
      int yy=y+ky-1; if(yy<0||yy>=S) continue;
      #pragma unroll
      for(int kx=0;kx<3;kx++){
        int xx=x+kx-1; if(xx<0||xx>=S) continue;
        acc += base[(long long)(yy*S+xx)*Dd + c]*wc3[ky*3+kx];
      }
    }
    out[c]=acc;
  }
}

__global__ void final_ln_k(const float* __restrict__ Hb, const float* __restrict__ g,
                           const float* __restrict__ bb, float* __restrict__ out){
  __shared__ float red[256];
  int b = blockIdx.x, t = threadIdx.x;
  const float* x = Hb + (long long)b*NT*Dd;
  float v0=x[t], v1=x[t+256];
  red[t]=v0+v1; __syncthreads();
  for(int o=128;o>0;o>>=1){ if(t<o) red[t]+=red[t+o]; __syncthreads(); }
  float mu = red[0]*(1.f/512.f); __syncthreads();
  float d0=v0-mu, d1=v1-mu;
  red[t]=d0*d0+d1*d1; __syncthreads();
  for(int o=128;o>0;o>>=1){ if(t<o) red[t]+=red[t+o]; __syncthreads(); }
  float rs = rsqrtf(red[0]*(1.f/512.f)+1e-5f);
  out[b*Dd + t]     = d0*rs*g[t]     + bb[t];
  out[b*Dd + t+256] = d1*rs*g[t+256] + bb[t+256];
}

// ---------------- host side ----------------
enum Cfg { CBIG, CN64, C64 };

static void tg(Cfg c, bool tb, GP p, int batches){
  int BM = (c==C64)?64:128;
  int BN = (c==CBIG)?128:64;
  dim3 g(p.N / BN, (p.M + BM - 1)/BM, batches * p.ksplit);
  if (c==CBIG){
    if (tb) tgemm_k<128,128,32,64,true ><<<g,256>>>(p);
    else    tgemm_k<128,128,32,64,false><<<g,256>>>(p);
  } else if (c==CN64){
    if (tb) tgemm_k<128,64,32,32,true ><<<g,256>>>(p);
    else    tgemm_k<128,64,32,32,false><<<g,256>>>(p);
  } else {
    if (tb) tgemm_k<64,64,16,32,true ><<<g,256>>>(p);
    else    tgemm_k<64,64,16,32,false><<<g,256>>>(p);
  }
}

struct Scratch {
  float *h0,*H,*H2,*XP,*QKV,*QL,*KL,*S1,*S3,*A2,*AZ,*T1,*T2,*Za,*Zb,*RED,*A3V,*W2,*PRT,*ATT;
};

static void attn_layer(float* Hbuf, const float* ng, const float* nb,
                       const float* qkvw, const float* ow, const float* ob,
                       const float* rw, const Scratch& s){
  float* Q  = s.QKV;
  float* Kp = s.QKV + QSZ;
  float* V  = s.QKV + 2*QSZ;
  GP p{};

  ln_pad_k<<<dim3(NP,Bb),256>>>(Hbuf, ng, nb, s.XP);

  // QKV projection + head scatter
  p = {s.XP,(long long)NP*Dd,Dd, qkvw,0,3*Dd, nullptr,0,0, NP,3*Dd,Dd, 1,2, nullptr,0.125f, s.QKV};
  tg(CBIG,false,p,Bb);

  landmarks_k<<<2048,256>>>(Q, Kp, s.QL, s.KL);

  // sim2 = QL @ KL^T
  p = {s.QL,(long long)LM*DH,DH, s.KL,(long long)LM*DH,DH, s.A2,(long long)LM*LM,LM, LM,LM,DH,1,0,nullptr,0.f,nullptr};
  tg(C64,true,p,32);
  softmax1_k<1><<<dim3(LM,32),256>>>(s.A2,(long long)LM*LM,LM);

  // pinv init
  pinv_part_k<<<32,256>>>(s.A2, s.RED);
  pinv_trans_k<<<32,256>>>(s.A2, s.RED, s.Za);
  float* zc = s.Za; float* zn = s.Zb;
  for(int it=0;it<6;it++){
    p = {s.A2,65536,LM, zc,65536,LM, s.AZ,65536,LM, LM,LM,LM,1,7,nullptr,0.f,s.T1};
    tg(C64,false,p,32);
    p = {s.AZ,65536,LM, s.T1,65536,LM, s.T2,65536,LM, LM,LM,LM,1,3,nullptr,15.f,nullptr};
    tg(C64,false,p,32);
    p = {s.AZ,65536,LM, s.T2,65536,LM, s.T1,65536,LM, LM,LM,LM,1,3,nullptr,13.f,nullptr};
    tg(C64,false,p,32);
    p = {zc,65536,LM, s.T1,65536,LM, zn,65536,LM, LM,LM,LM,1,4,nullptr,0.25f,nullptr};
    tg(C64,false,p,32);
    float* t=zc; zc=zn; zn=t;
  }

  // sim1 = q @ KL^T (valid tokens only)
  p = {Q+(long long)PADT*DH,(long long)NP*DH,DH, s.KL,(long long)LM*DH,DH,
       s.S1+(long long)PADT*LM,(long long)NP*LM,LM, NT,LM,DH,1,0,nullptr,0.f,nullptr};
  tg(CBIG,true,p,32);
  softmax1_k<1><<<dim3(NT,32),256>>>(s.S1+(long long)PADT*LM,(long long)NP*LM,LM);

  // sim3 = QL @ K^T
  p = {s.QL,(long long)LM*DH,DH, Kp,(long long)NP*DH,DH, s.S3,(long long)LM*NP,NP, LM,NP,DH,1,0,nullptr,0.f,nullptr};
  tg(CBIG,true,p,32);
  softmax1_k<25><<<dim3(LM,32),256>>>(s.S3,(long long)LM*NP,NP);

  // a3v = a3 @ v (split-K 8)
  p = {s.S3,(long long)LM*NP,NP, V,(long long)NP*DH,DH, s.PRT,(long long)LM*DH,DH, LM,DH,NP,8,0,nullptr,0.f,nullptr};
  tg(C64,false,p,32);
  reduce8_k<<<2048,256>>>(s.PRT, s.A3V);

  // w2 = Z @ a3v
  p = {zc,65536,LM, s.A3V,(long long)LM*DH,DH, s.W2,(long long)LM*DH,DH, LM,DH,LM,1,0,nullptr,0.f,nullptr};
  tg(C64,false,p,32);

  // attn = a1 @ w2 -> token-major scatter
  p = {s.S1+(long long)PADT*LM,(long long)NP*LM,LM, s.W2,(long long)LM*DH,DH, nullptr,0,0,
       NT,DH,LM,1,5,nullptr,0.f,s.ATT};
  tg(CN64,false,p,32);

  dwconv_k<<<dim3(1566,32),256>>>(V, rw, s.ATT);

  // out proj + residual add
  p = {s.ATT+(long long)PADT*Dd,(long long)NP*Dd,Dd, ow,0,Dd, Hbuf,(long long)NT*Dd,Dd,
       NT,Dd,Dd,1,6,ob,0.f,nullptr};
  tg(CBIG,false,p,Bb);
}

extern "C" void kernel_launch(void* const* d_in, const int* in_sizes, int n_in,
                              void* d_out, int out_size){
  const float* x        = (const float*)d_in[0];
  const float* fc1_w    = (const float*)d_in[1];
  const float* fc1_b    = (const float*)d_in[2];
  const float* cls_tok  = (const float*)d_in[3];
  const float* l1_ng    = (const float*)d_in[4];
  const float* l1_nb    = (const float*)d_in[5];
  const float* l1_qkv   = (const float*)d_in[6];
  const float* l1_ow    = (const float*)d_in[7];
  const float* l1_ob    = (const float*)d_in[8];
  const float* l1_rw    = (const float*)d_in[9];
  const float* ct_w7    = (const float*)d_in[10];
  const float* ct_b7    = (const float*)d_in[11];
  const float* ct_w5    = (const float*)d_in[12];
  const float* ct_b5    = (const float*)d_in[13];
  const float* ct_w3    = (const float*)d_in[14];
  const float* ct_b3    = (const float*)d_in[15];
  const float* pth_w7   = (const float*)d_in[16];
  const float* pth_b7   = (const float*)d_in[17];
  const float* pth_w5   = (const float*)d_in[18];
  const float* pth_b5   = (const float*)d_in[19];
  const float* pth_w3   = (const float*)d_in[20];
  const float* pth_b3   = (const float*)d_in[21];
  const float* l2_ng    = (const float*)d_in[22];
  const float* l2_nb    = (const float*)d_in[23];
  const float* l2_qkv   = (const float*)d_in[24];
  const float* l2_ow    = (const float*)d_in[25];
  const float* l2_ob    = (const float*)d_in[26];
  const float* l2_rw    = (const float*)d_in[27];
  const float* norm_g   = (const float*)d_in[28];
  const float* norm_b   = (const float*)d_in[29];

  Scratch s;
  cudaGetSymbolAddress((void**)&s.h0 , g_h0 );
  cudaGetSymbolAddress((void**)&s.H  , g_H  );
  cudaGetSymbolAddress((void**)&s.H2 , g_H2 );
  cudaGetSymbolAddress((void**)&s.XP , g_XP );
  cudaGetSymbolAddress((void**)&s.QKV, g_QKV);
  cudaGetSymbolAddress((void**)&s.QL , g_QL );
  cudaGetSymbolAddress((void**)&s.KL , g_KL );
  cudaGetSymbolAddress((void**)&s.S1 , g_S1 );
  cudaGetSymbolAddress((void**)&s.S3 , g_S3 );
  cudaGetSymbolAddress((void**)&s.A2 , g_A2 );
  cudaGetSymbolAddress((void**)&s.AZ , g_AZ );
  cudaGetSymbolAddress((void**)&s.T1 , g_T1 );
  cudaGetSymbolAddress((void**)&s.T2 , g_T2 );
  cudaGetSymbolAddress((void**)&s.Za , g_Za );
  cudaGetSymbolAddress((void**)&s.Zb , g_Zb );
  cudaGetSymbolAddress((void**)&s.RED, g_RED);
  cudaGetSymbolAddress((void**)&s.A3V, g_A3V);
  cudaGetSymbolAddress((void**)&s.W2 , g_W2 );
  cudaGetSymbolAddress((void**)&s.PRT, g_PRT);
  cudaGetSymbolAddress((void**)&s.ATT, g_ATT);

  GP p{};
  // fc1 + relu
  p = {x,0,Lf, fc1_w,0,Dd, s.h0,0,Dd, Bb*NIN,Dd,Lf, 1,1, fc1_b,0.f,nullptr};
  tg(CBIG,false,p,1);

  build_H_k<<<dim3(NT,Bb),256>>>(s.h0, cls_tok, s.H);

  attn_layer(s.H, l1_ng, l1_nb, l1_qkv, l1_ow, l1_ob, l1_rw, s);

  copyrows_k<<<dim3(11,Bb),256>>>(s.H, s.H2);
  ppeg_k<<<dim3(169 ,Bb),128>>>(s.H, s.H2, 11 , 13, ct_w7 ,ct_b7 ,ct_w5 ,ct_b5 ,ct_w3 ,ct_b3 );
  ppeg_k<<<dim3(6084,Bb),128>>>(s.H, s.H2, 180, 78, pth_w7,pth_b7,pth_w5,pth_b5,pth_w3,pth_b3);

  attn_layer(s.H2, l2_ng, l2_nb, l2_qkv, l2_ow, l2_ob, l2_rw, s);

  final_ln_k<<<Bb,256>>>(s.H2, norm_g, norm_b, (float*)d_out);
}